// round 8
// baseline (speedup 1.0000x reference)
#include <cuda_runtime.h>

// LSTMModel: B=1024, T=256, I=5, H=64, L=3, O=1, fp32.
// R7: warp-specialized fusion. Layers 0/1 run lstm_fused: 152 CTAs x 512
// threads (1/SM). Warps 0-7 = R4-style recurrence (w_hh rows in regs, smem
// gates, double-buffered h, 2 BARs/step, no g_h traffic). Warps 8-15 = next
// layer's input projection: w_ih_next rows in regs, consume h(t-1) from smem
// one step behind, write g_xg for the next layer. Layer 2 = R4 rec (MODE 2).
// Removes xg_gemm64, transpose_w, and the g_h round-trip entirely.

#define B_SZ 1024
#define T_SZ 256
#define I_SZ 5
#define H_SZ 64
#define G_SZ 256   // 4*H

// fused kernel grid: 152 CTAs; first 112 own 7 rows, remaining 40 own 6
#define GRID_F 152
#define N7     112        // 112*7 + 40*6 = 1024

// layer-2 rec grid (R4 balanced): 304 CTAs; first 112 own 4 rows, rest 3
#define N4       112
#define GRID_REC 304      // 112*4 + 192*3 = 1024

typedef unsigned long long u64;

__device__ float g_xga[(size_t)B_SZ * T_SZ * G_SZ];  // xg for layer 1
__device__ float g_xgb[(size_t)B_SZ * T_SZ * G_SZ];  // xg for layer 2
__device__ float g_h  [B_SZ * H_SZ];                 // layer-2 h_last (compact)

__device__ __forceinline__ u64 ffma2(u64 a, u64 b, u64 c) {
    u64 d;
    asm("fma.rn.f32x2 %0, %1, %2, %3;" : "=l"(d) : "l"(a), "l"(b), "l"(c));
    return d;
}
__device__ __forceinline__ u64 pack2(float lo, float hi) {
    u64 d;
    asm("mov.b64 %0, {%1, %2};" : "=l"(d) : "f"(lo), "f"(hi));
    return d;
}
__device__ __forceinline__ float sum2(u64 v) {
    float lo, hi;
    asm("mov.b64 {%0, %1}, %2;" : "=f"(lo), "=f"(hi) : "l"(v));
    return lo + hi;
}

__device__ __forceinline__ float sigf(float x) {
    return __fdividef(1.0f, 1.0f + __expf(-x));
}
__device__ __forceinline__ float tanh_fast(float x) {
    float ax = fabsf(x);
    float e  = __expf(-2.0f * ax);
    float r  = __fdividef(1.0f - e, 1.0f + e);
    return copysignf(r, x);
}
__device__ __forceinline__ float cell_update(const float* grow, int je, float& c)
{
    float iv = sigf(grow[je]);
    float fv = sigf(grow[64 + je]);
    float gv = tanh_fast(grow[128 + je]);
    float ov = sigf(grow[192 + je]);
    c = fmaf(fv, c, iv * gv);
    return ov * tanh_fast(c);
}

// ---------------------------------------------------------------------------
// Fused layer kernel (layers 0 and 1). 152 CTAs x 512 threads, 1 CTA/SM.
//   threads   0-255 (rec): gate column `col`; w_hh[col] register-resident.
//   threads 256-511 (xg) : gate column `col` of the NEXT layer's w_ih;
//                          computes xg_next(tau=step-1) from hbuf each step.
// h double-buffered: h(t) lives in hbuf[t&1]; step t reads hbuf[(t+1)&1].
// MODE 0: layer 0 (x via K=5 weights, writes g_xga).
// MODE 1: layer 1 (reads g_xga, writes g_xgb).
// ---------------------------------------------------------------------------
template<int MODE>
__global__ __launch_bounds__(512, 1) void lstm_fused(
    const float* __restrict__ w_hh,
    const float* __restrict__ x,      // MODE 0 only
    const float* __restrict__ w_ih,   // MODE 0 only [256,5]
    const float* __restrict__ b_ih,   // MODE 0 only
    const float* __restrict__ b_hh,   // MODE 0 only
    const float* __restrict__ w_ihn,  // next layer w_ih [256,64]
    const float* __restrict__ b_ihn,
    const float* __restrict__ b_hhn)
{
    __shared__ __align__(16) float hbuf[2][7][H_SZ];   // 3.5 KB
    __shared__ float gates_s[7][G_SZ];                 // 7 KB
    __shared__ float xs[2][7][I_SZ];                   // MODE-0 x staging

    const int t     = threadIdx.x;
    const int col   = t & 255;
    const bool isrec = (t < 256);
    const int bid   = blockIdx.x;
    const bool r7   = (bid < N7);
    const int b0    = r7 ? bid * 7 : N7 * 7 + (bid - N7) * 6;
    const int rows  = r7 ? 7 : 6;

    const float* g_in  = g_xga;                       // MODE 1 input
    float*       g_out = (MODE == 0) ? g_xga : g_xgb;

    // register-resident weight rows: rec -> w_hh[col], xg -> w_ihn[col]
    u64 w2[32];
    {
        const float* wsrc = isrec ? (w_hh + col * H_SZ) : (w_ihn + col * H_SZ);
        const ulonglong2* wv = (const ulonglong2*)wsrc;
#pragma unroll
        for (int q = 0; q < 16; q++) {
            ulonglong2 v = wv[q];
            w2[2 * q]     = v.x;
            w2[2 * q + 1] = v.y;
        }
    }

    float wx[MODE == 0 ? I_SZ : 1];
    float bias = 0.0f;   // rec MODE-0 input bias
    float biasn = 0.0f;  // xg next-layer bias
    if (isrec) {
        if (MODE == 0) {
#pragma unroll
            for (int k = 0; k < I_SZ; k++) wx[k] = w_ih[col * I_SZ + k];
            bias = b_ih[col] + b_hh[col];
            if (t < 7 * I_SZ) {
                int r = t / I_SZ, k = t % I_SZ;
                if (r < rows)
                    xs[0][r][k] = x[((size_t)(b0 + r) * T_SZ) * I_SZ + k];
            }
        }
    } else {
        biasn = b_ihn[col] + b_hhn[col];
    }

    // zero both h buffers
    for (int v = t; v < 2 * 7 * H_SZ; v += 512) ((float*)hbuf)[v] = 0.0f;

    // rec epilogue cells: cell A = (t>>6, t&63); cell B = (4 + (t>>6), t&63)
    const int r0e = t >> 6, je = t & 63;
    const bool hasB = isrec && (t < (rows - 4) * 64);
    float c0 = 0.0f, c1 = 0.0f;

    // MODE-1 rec: prefetch xg for step 0
    float xn[MODE == 1 ? 7 : 1];
    if (MODE == 1 && isrec) {
#pragma unroll
        for (int r = 0; r < 6; r++)
            xn[r] = g_in[((size_t)(b0 + r) * T_SZ) * G_SZ + col];
        xn[6] = r7 ? g_in[((size_t)(b0 + 6) * T_SZ) * G_SZ + col] : 0.0f;
    }

    u64 accn[7];   // xg accumulators (persist across the mid-step barrier)

    __syncthreads();

    for (int step = 0; step < T_SZ; step++) {
        const int rb = (step + 1) & 1;   // buffer holding h(step-1)
        const int wb = step & 1;         // buffer receiving h(step)

        // ---------------- phase 1 ----------------
        if (isrec) {
            u64 acc[7];
            if (MODE == 0) {
                const int cur = step & 1;
#pragma unroll
                for (int r = 0; r < 7; r++) {
                    float s = bias;
#pragma unroll
                    for (int k = 0; k < I_SZ; k++)
                        s = fmaf(xs[cur][r][k], wx[k], s);
                    acc[r] = pack2(s, 0.0f);
                }
                if (step + 1 < T_SZ && t < 7 * I_SZ) {
                    int r = t / I_SZ, k = t % I_SZ;
                    if (r < rows)
                        xs[cur ^ 1][r][k] =
                            x[((size_t)(b0 + r) * T_SZ + step + 1) * I_SZ + k];
                }
            } else {
#pragma unroll
                for (int r = 0; r < 7; r++) acc[r] = pack2(xn[r], 0.0f);
                if (step + 1 < T_SZ) {
#pragma unroll
                    for (int r = 0; r < 6; r++)
                        xn[r] = g_in[((size_t)(b0 + r) * T_SZ + step + 1) * G_SZ + col];
                    if (r7)
                        xn[6] = g_in[((size_t)(b0 + 6) * T_SZ + step + 1) * G_SZ + col];
                }
            }

            const ulonglong2* h2 = (const ulonglong2*)&hbuf[rb][0][0];
#pragma unroll
            for (int q = 0; q < 16; q++) {
                const u64 wa = w2[2 * q], wb2 = w2[2 * q + 1];
#pragma unroll
                for (int r = 0; r < 6; r++) {
                    ulonglong2 p = h2[r * 16 + q];
                    acc[r] = ffma2(p.x, wa,  acc[r]);
                    acc[r] = ffma2(p.y, wb2, acc[r]);
                }
            }
            if (r7) {
#pragma unroll
                for (int q = 0; q < 16; q++) {
                    ulonglong2 p = h2[96 + q];
                    acc[6] = ffma2(p.x, w2[2 * q],     acc[6]);
                    acc[6] = ffma2(p.y, w2[2 * q + 1], acc[6]);
                }
            }
#pragma unroll
            for (int r = 0; r < 6; r++) gates_s[r][col] = sum2(acc[r]);
            if (r7) gates_s[6][col] = sum2(acc[6]);
        } else if (step > 0) {
            // xg rows 0-3 for tau = step-1 (h(step-1) = hbuf[rb], stable)
            const ulonglong2* h2 = (const ulonglong2*)&hbuf[rb][0][0];
#pragma unroll
            for (int r = 0; r < 4; r++) accn[r] = pack2(biasn, 0.0f);
#pragma unroll
            for (int q = 0; q < 16; q++) {
                const u64 wa = w2[2 * q], wb2 = w2[2 * q + 1];
#pragma unroll
                for (int r = 0; r < 4; r++) {
                    ulonglong2 p = h2[r * 16 + q];
                    accn[r] = ffma2(p.x, wa,  accn[r]);
                    accn[r] = ffma2(p.y, wb2, accn[r]);
                }
            }
        }
        __syncthreads();

        // ---------------- phase 2 ----------------
        if (isrec) {
            float hv = cell_update(&gates_s[r0e][0], je, c0);
            hbuf[wb][r0e][je] = hv;
            if (hasB) {
                float hv1 = cell_update(&gates_s[4 + r0e][0], je, c1);
                hbuf[wb][4 + r0e][je] = hv1;
            }
        } else if (step > 0) {
            const int tau = step - 1;
            const ulonglong2* h2 = (const ulonglong2*)&hbuf[rb][0][0];
            // rows 4..6
            accn[4] = pack2(biasn, 0.0f);
            accn[5] = pack2(biasn, 0.0f);
            accn[6] = pack2(biasn, 0.0f);
#pragma unroll
            for (int q = 0; q < 16; q++) {
                const u64 wa = w2[2 * q], wb2 = w2[2 * q + 1];
                ulonglong2 p4 = h2[64 + q];
                accn[4] = ffma2(p4.x, wa,  accn[4]);
                accn[4] = ffma2(p4.y, wb2, accn[4]);
                ulonglong2 p5 = h2[80 + q];
                accn[5] = ffma2(p5.x, wa,  accn[5]);
                accn[5] = ffma2(p5.y, wb2, accn[5]);
            }
            if (r7) {
#pragma unroll
                for (int q = 0; q < 16; q++) {
                    ulonglong2 p6 = h2[96 + q];
                    accn[6] = ffma2(p6.x, w2[2 * q],     accn[6]);
                    accn[6] = ffma2(p6.y, w2[2 * q + 1], accn[6]);
                }
            }
            // store xg(tau) for all rows (coalesced: 256 consecutive cols)
#pragma unroll
            for (int r = 0; r < 6; r++)
                g_out[((size_t)(b0 + r) * T_SZ + tau) * G_SZ + col] = sum2(accn[r]);
            if (r7)
                g_out[((size_t)(b0 + 6) * T_SZ + tau) * G_SZ + col] = sum2(accn[6]);
        }
        __syncthreads();
    }

    // tail: xg for tau = T-1 (h(T-1) lives in hbuf[(T_SZ-1)&1] = hbuf[1])
    if (!isrec) {
        const ulonglong2* h2 = (const ulonglong2*)&hbuf[1][0][0];
        u64 a[7];
#pragma unroll
        for (int r = 0; r < 7; r++) a[r] = pack2(biasn, 0.0f);
#pragma unroll
        for (int q = 0; q < 16; q++) {
            const u64 wa = w2[2 * q], wb2 = w2[2 * q + 1];
#pragma unroll
            for (int r = 0; r < 6; r++) {
                ulonglong2 p = h2[r * 16 + q];
                a[r] = ffma2(p.x, wa,  a[r]);
                a[r] = ffma2(p.y, wb2, a[r]);
            }
        }
        if (r7) {
#pragma unroll
            for (int q = 0; q < 16; q++) {
                ulonglong2 p = h2[96 + q];
                a[6] = ffma2(p.x, w2[2 * q],     a[6]);
                a[6] = ffma2(p.y, w2[2 * q + 1], a[6]);
            }
        }
#pragma unroll
        for (int r = 0; r < 6; r++)
            g_out[((size_t)(b0 + r) * T_SZ + (T_SZ - 1)) * G_SZ + col] = sum2(a[r]);
        if (r7)
            g_out[((size_t)(b0 + 6) * T_SZ + (T_SZ - 1)) * G_SZ + col] = sum2(a[6]);
    }
}

// ---------------------------------------------------------------------------
// Layer-2 recurrence (R4 structure, MODE 2): 304 CTAs x 256 threads,
// 2 CTAs/SM, balanced 4/3 rows. Reads g_xgb, writes only h(T-1) compact.
// ---------------------------------------------------------------------------
__global__ __launch_bounds__(256, 2) void lstm_rec2(const float* __restrict__ w_hh)
{
    __shared__ __align__(16) float h_s[4][H_SZ];
    __shared__ float gates_s[4][G_SZ];
    const int t    = threadIdx.x;
    const int bid  = blockIdx.x;
    const bool r4  = (bid < N4);
    const int b0   = r4 ? bid * 4 : N4 * 4 + (bid - N4) * 3;
    const int rows = r4 ? 4 : 3;

    u64 w2[32];
    {
        const ulonglong2* wv = (const ulonglong2*)(w_hh + t * H_SZ);
#pragma unroll
        for (int q = 0; q < 16; q++) {
            ulonglong2 v = wv[q];
            w2[2 * q]     = v.x;
            w2[2 * q + 1] = v.y;
        }
    }

    ((float*)h_s)[t] = 0.0f;

    const int re = t >> 6, je = t & 63;
    const bool cell = (t < rows * 64);
    float c = 0.0f;

    float xn[4];
#pragma unroll
    for (int r = 0; r < 3; r++)
        xn[r] = g_xgb[((size_t)(b0 + r) * T_SZ) * G_SZ + t];
    xn[3] = r4 ? g_xgb[((size_t)(b0 + 3) * T_SZ) * G_SZ + t] : 0.0f;

    __syncthreads();

    for (int step = 0; step < T_SZ; step++) {
        u64 acc2[4];
#pragma unroll
        for (int r = 0; r < 4; r++) acc2[r] = pack2(xn[r], 0.0f);

        if (step + 1 < T_SZ) {
#pragma unroll
            for (int r = 0; r < 3; r++)
                xn[r] = g_xgb[((size_t)(b0 + r) * T_SZ + step + 1) * G_SZ + t];
            if (r4)
                xn[3] = g_xgb[((size_t)(b0 + 3) * T_SZ + step + 1) * G_SZ + t];
        }

        const ulonglong2* h2 = (const ulonglong2*)&h_s[0][0];
#pragma unroll
        for (int q = 0; q < 16; q++) {
            const u64 wa = w2[2 * q], wb = w2[2 * q + 1];
            ulonglong2 p0 = h2[q];
            acc2[0] = ffma2(p0.x, wa, acc2[0]);
            acc2[0] = ffma2(p0.y, wb, acc2[0]);
            ulonglong2 p1 = h2[16 + q];
            acc2[1] = ffma2(p1.x, wa, acc2[1]);
            acc2[1] = ffma2(p1.y, wb, acc2[1]);
            ulonglong2 p2 = h2[32 + q];
            acc2[2] = ffma2(p2.x, wa, acc2[2]);
            acc2[2] = ffma2(p2.y, wb, acc2[2]);
        }
        if (r4) {
#pragma unroll
            for (int q = 0; q < 16; q++) {
                ulonglong2 p3 = h2[48 + q];
                acc2[3] = ffma2(p3.x, w2[2 * q],     acc2[3]);
                acc2[3] = ffma2(p3.y, w2[2 * q + 1], acc2[3]);
            }
        }
        gates_s[0][t] = sum2(acc2[0]);
        gates_s[1][t] = sum2(acc2[1]);
        gates_s[2][t] = sum2(acc2[2]);
        if (r4) gates_s[3][t] = sum2(acc2[3]);
        __syncthreads();

        if (cell) {
            float hv = cell_update(&gates_s[re][0], je, c);
            h_s[re][je] = hv;
            if (step == T_SZ - 1)
                g_h[(b0 + re) * H_SZ + je] = hv;
        }
        __syncthreads();
    }
}

// ---------------------------------------------------------------------------
// Final FC: out[b] = h_last[b,:] . w_fc + b_fc   (O=1)
// ---------------------------------------------------------------------------
__global__ __launch_bounds__(256) void fc_kernel(const float* __restrict__ wfc,
                                                 const float* __restrict__ bfc,
                                                 float* __restrict__ out)
{
    int b = blockIdx.x * 256 + threadIdx.x;
    float acc = bfc[0];
#pragma unroll
    for (int q = 0; q < 16; q++) {
        float4 hv = *(const float4*)&g_h[b * H_SZ + q * 4];
        float4 wv = *(const float4*)&wfc[q * 4];
        acc = fmaf(hv.x, wv.x, acc);
        acc = fmaf(hv.y, wv.y, acc);
        acc = fmaf(hv.z, wv.z, acc);
        acc = fmaf(hv.w, wv.w, acc);
    }
    out[b] = acc;
}

// ---------------------------------------------------------------------------
extern "C" void kernel_launch(void* const* d_in, const int* in_sizes, int n_in,
                              void* d_out, int out_size)
{
    (void)in_sizes; (void)n_in; (void)out_size;
    const float* x     = (const float*)d_in[0];
    const float* w_ih0 = (const float*)d_in[1];
    const float* w_hh0 = (const float*)d_in[2];
    const float* b_ih0 = (const float*)d_in[3];
    const float* b_hh0 = (const float*)d_in[4];
    const float* w_ih1 = (const float*)d_in[5];
    const float* w_hh1 = (const float*)d_in[6];
    const float* b_ih1 = (const float*)d_in[7];
    const float* b_hh1 = (const float*)d_in[8];
    const float* w_ih2 = (const float*)d_in[9];
    const float* w_hh2 = (const float*)d_in[10];
    const float* b_ih2 = (const float*)d_in[11];
    const float* b_hh2 = (const float*)d_in[12];
    const float* w_fc  = (const float*)d_in[13];
    const float* b_fc  = (const float*)d_in[14];
    float* out = (float*)d_out;

    // layer 0 rec + layer 1 xg  -> g_xga
    lstm_fused<0><<<GRID_F, 512>>>(w_hh0, x, w_ih0, b_ih0, b_hh0,
                                   w_ih1, b_ih1, b_hh1);
    // layer 1 rec (g_xga) + layer 2 xg -> g_xgb
    lstm_fused<1><<<GRID_F, 512>>>(w_hh1, nullptr, nullptr, nullptr, nullptr,
                                   w_ih2, b_ih2, b_hh2);
    // layer 2 rec (g_xgb) -> g_h (last step only)
    lstm_rec2<<<GRID_REC, 256>>>(w_hh2);

    // final projection
    fc_kernel<<<B_SZ / 256, 256>>>(w_fc, b_fc, out);
}

// round 9
// speedup vs baseline: 1.1758x; 1.1758x over previous
#include <cuda_runtime.h>

// LSTMModel: B=1024, T=256, I=5, H=64, L=3, O=1, fp32.
// R8: exact R4 structure (best known) + (1) anti-phase stagger of the two
// co-resident rec CTAs (bid>=152 spins ~1200cyc so one CTA GEMMs while its
// SM-partner runs the MUFU epilogue), (2) fc fused into layer-2 rec tail,
// (3) both w_ih transposes in one upfront launch.

#define B_SZ 1024
#define T_SZ 256
#define I_SZ 5
#define H_SZ 64
#define G_SZ 256   // 4*H
#define N4   112           // CTAs carrying 4 rows; rest carry 3
#define GRID_REC 304       // 112*4 + 192*3 = 1024
#define STAG_CYC 1200

typedef unsigned long long u64;

__device__ float g_xg[(size_t)B_SZ * T_SZ * G_SZ];  // gate preactivations (layers 1,2)
__device__ float g_h [(size_t)B_SZ * T_SZ * H_SZ];  // layer outputs
__device__ float g_wT1[H_SZ * G_SZ];                // transposed w_ih1
__device__ float g_wT2[H_SZ * G_SZ];                // transposed w_ih2

__device__ __forceinline__ u64 ffma2(u64 a, u64 b, u64 c) {
    u64 d;
    asm("fma.rn.f32x2 %0, %1, %2, %3;" : "=l"(d) : "l"(a), "l"(b), "l"(c));
    return d;
}
__device__ __forceinline__ u64 pack2(float lo, float hi) {
    u64 d;
    asm("mov.b64 %0, {%1, %2};" : "=l"(d) : "f"(lo), "f"(hi));
    return d;
}
__device__ __forceinline__ float sum2(u64 v) {
    float lo, hi;
    asm("mov.b64 {%0, %1}, %2;" : "=f"(lo), "=f"(hi) : "l"(v));
    return lo + hi;
}

__device__ __forceinline__ float sigf(float x) {
    return __fdividef(1.0f, 1.0f + __expf(-x));
}
__device__ __forceinline__ float tanh_fast(float x) {
    float ax = fabsf(x);
    float e  = __expf(-2.0f * ax);
    float r  = __fdividef(1.0f - e, 1.0f + e);
    return copysignf(r, x);
}

// ---------------------------------------------------------------------------
// Transpose w_ih1 AND w_ih2 [256,64] -> g_wT1/g_wT2 [64,256] in one launch.
// ---------------------------------------------------------------------------
__global__ __launch_bounds__(256) void transpose_w2(
    const float* __restrict__ w1, const float* __restrict__ w2)
{
    int idx = blockIdx.x * 256 + threadIdx.x;  // < 32768
    int l = idx >> 14, r = idx & 16383;
    int g = r >> 6, k = r & 63;
    if (l == 0) g_wT1[k * G_SZ + g] = w1[r];
    else        g_wT2[k * G_SZ + g] = w2[r];
}

// ---------------------------------------------------------------------------
// Layers 1/2 input projection (R4-exact, wT selected by `which`).
// ---------------------------------------------------------------------------
#define XG_W_PITCH 260
#define XG_SMEM_BYTES (64 * 64 * 8 + 64 * XG_W_PITCH * 4)

__global__ __launch_bounds__(256, 2) void xg_gemm64(
    const float* __restrict__ b_ih, const float* __restrict__ b_hh, int which)
{
    extern __shared__ __align__(16) unsigned char smraw[];
    u64   (*a2_s)[64]        = (u64(*)[64])smraw;
    float (*w_s)[XG_W_PITCH] = (float(*)[XG_W_PITCH])(smraw + 64 * 64 * 8);
    const float* wT = which ? g_wT2 : g_wT1;

    const int t    = threadIdx.x;
    const int row0 = blockIdx.x * 64;
    const int tcol = t & 31, trow = t >> 5;
    const int g0   = tcol * 8;

#pragma unroll
    for (int u = 0; u < 4; u++) {
        int v = u * 256 + t;
        int r = v >> 4, kq = v & 15;
        float4 d = *(const float4*)&g_h[(size_t)(row0 + r) * H_SZ + kq * 4];
        ulonglong2 e0, e1;
        e0.x = pack2(d.x, d.x); e0.y = pack2(d.y, d.y);
        e1.x = pack2(d.z, d.z); e1.y = pack2(d.w, d.w);
        *(ulonglong2*)&a2_s[r][kq * 4]     = e0;
        *(ulonglong2*)&a2_s[r][kq * 4 + 2] = e1;
    }
#pragma unroll
    for (int u = 0; u < 16; u++) {
        int v = u * 256 + t;
        int k = v >> 6, gq = v & 63;
        float4 d = *(const float4*)&wT[k * G_SZ + gq * 4];
        *(float4*)&w_s[k][gq * 4] = d;
    }

    u64 acc2[8][4];
#pragma unroll
    for (int jp = 0; jp < 4; jp++) {
        float blo = b_ih[g0 + 2 * jp]     + b_hh[g0 + 2 * jp];
        float bhi = b_ih[g0 + 2 * jp + 1] + b_hh[g0 + 2 * jp + 1];
        u64 bp = pack2(blo, bhi);
#pragma unroll
        for (int ii = 0; ii < 8; ii++) acc2[ii][jp] = bp;
    }

    __syncthreads();

#pragma unroll 4
    for (int k = 0; k < 64; k++) {
        u64 adup[8];
#pragma unroll
        for (int ii = 0; ii < 8; ii++)
            adup[ii] = a2_s[trow * 8 + ii][k];
        ulonglong2 bv0 = *(const ulonglong2*)&w_s[k][g0];
        ulonglong2 bv1 = *(const ulonglong2*)&w_s[k][g0 + 4];
        u64 bp[4] = {bv0.x, bv0.y, bv1.x, bv1.y};
#pragma unroll
        for (int ii = 0; ii < 8; ii++)
#pragma unroll
            for (int jp = 0; jp < 4; jp++)
                acc2[ii][jp] = ffma2(adup[ii], bp[jp], acc2[ii][jp]);
    }

#pragma unroll
    for (int ii = 0; ii < 8; ii++) {
        size_t base = (size_t)(row0 + trow * 8 + ii) * G_SZ + g0;
        ulonglong2 o0, o1;
        o0.x = acc2[ii][0]; o0.y = acc2[ii][1];
        o1.x = acc2[ii][2]; o1.y = acc2[ii][3];
        *(ulonglong2*)&g_xg[base]     = o0;
        *(ulonglong2*)&g_xg[base + 4] = o1;
    }
}

// ---------------------------------------------------------------------------
// Recurrent scan (R4-exact + stagger + fused fc in mode 2).
// Balanced 304-CTA grid (112x4 + 192x3 rows), 256 threads, 2 CTAs/SM.
// CTAs with bid>=152 (second residency wave -> SM partners of bid-152) spin
// ~STAG_CYC before the loop so the two co-resident CTAs run anti-phased.
// ---------------------------------------------------------------------------
__global__ __launch_bounds__(256, 2) void lstm_rec(
    const float* __restrict__ w_hh,
    const float* __restrict__ x,      // mode 0 only
    const float* __restrict__ w_ih,   // mode 0 only [256,5]
    const float* __restrict__ b_ih,   // mode 0 only
    const float* __restrict__ b_hh,   // mode 0 only
    const float* __restrict__ wfc,    // mode 2 only
    const float* __restrict__ bfc,    // mode 2 only
    float* __restrict__ out,          // mode 2 only
    int mode)
{
    __shared__ __align__(16) float h_s[4][H_SZ];     // 1 KB
    __shared__ float gates_s[4][G_SZ];               // 4 KB
    __shared__ float xs[2][4][8];                    // mode-0 x staging
    const int t   = threadIdx.x;                     // gate column
    const int bid = blockIdx.x;
    const bool r4 = (bid < N4);
    const int b0  = r4 ? bid * 4 : N4 * 4 + (bid - N4) * 3;
    const int rows = r4 ? 4 : 3;

    // anti-phase stagger for the second residency wave
    if (bid >= 152) {
        long long s0 = clock64();
        while (clock64() - s0 < STAG_CYC) {}
    }

    // register-resident recurrent weight pairs (w_hh row t)
    u64 w2[32];
    {
        const ulonglong2* wv = (const ulonglong2*)(w_hh + t * H_SZ);
#pragma unroll
        for (int q = 0; q < 16; q++) {
            ulonglong2 v = wv[q];
            w2[2 * q]     = v.x;
            w2[2 * q + 1] = v.y;
        }
    }

    // mode-0: input weights + bias + step-0 x staging
    float wx[I_SZ];
    float bias = 0.0f;
    if (mode == 0) {
#pragma unroll
        for (int k = 0; k < I_SZ; k++) wx[k] = w_ih[t * I_SZ + k];
        bias = b_ih[t] + b_hh[t];
        if (t < 4 * I_SZ) {
            int r = t / I_SZ, k = t % I_SZ;
            if (r < rows)
                xs[0][r][k] = x[((size_t)(b0 + r) * T_SZ) * I_SZ + k];
        }
    }

    ((float*)h_s)[t] = 0.0f;

    const int re = t >> 6, je = t & 63;
    const bool cell = (t < rows * 64);
    float c = 0.0f;
    float h_last = 0.0f;

    float xn[4];
    if (mode != 0) {
#pragma unroll
        for (int r = 0; r < 3; r++)
            xn[r] = g_xg[((size_t)(b0 + r) * T_SZ) * G_SZ + t];
        xn[3] = r4 ? g_xg[((size_t)(b0 + 3) * T_SZ) * G_SZ + t] : 0.0f;
    }

    __syncthreads();

    for (int step = 0; step < T_SZ; step++) {
        u64 acc2[4];
        if (mode == 0) {
            const int cur = step & 1;
            float a0 = bias, a1 = bias, a2v = bias, a3 = bias;
#pragma unroll
            for (int k = 0; k < I_SZ; k++) {
                a0  = fmaf(xs[cur][0][k], wx[k], a0);
                a1  = fmaf(xs[cur][1][k], wx[k], a1);
                a2v = fmaf(xs[cur][2][k], wx[k], a2v);
                a3  = fmaf(xs[cur][3][k], wx[k], a3);
            }
            acc2[0] = pack2(a0, 0.0f);  acc2[1] = pack2(a1, 0.0f);
            acc2[2] = pack2(a2v, 0.0f); acc2[3] = pack2(a3, 0.0f);
            if (step + 1 < T_SZ && t < 4 * I_SZ) {
                int r = t / I_SZ, k = t % I_SZ;
                if (r < rows)
                    xs[cur ^ 1][r][k] = x[((size_t)(b0 + r) * T_SZ + step + 1) * I_SZ + k];
            }
        } else {
#pragma unroll
            for (int r = 0; r < 4; r++) acc2[r] = pack2(xn[r], 0.0f);
            if (step + 1 < T_SZ) {
#pragma unroll
                for (int r = 0; r < 3; r++)
                    xn[r] = g_xg[((size_t)(b0 + r) * T_SZ + step + 1) * G_SZ + t];
                if (r4)
                    xn[3] = g_xg[((size_t)(b0 + 3) * T_SZ + step + 1) * G_SZ + t];
            }
        }

        // GEMM: gates[r][t] += sum_k h[r][k] * w_hh[t][k]
        const ulonglong2* h2 = (const ulonglong2*)&h_s[0][0];
#pragma unroll
        for (int q = 0; q < 16; q++) {
            const u64 wa = w2[2 * q], wb = w2[2 * q + 1];
            ulonglong2 p0 = h2[q];
            acc2[0] = ffma2(p0.x, wa, acc2[0]);
            acc2[0] = ffma2(p0.y, wb, acc2[0]);
            ulonglong2 p1 = h2[16 + q];
            acc2[1] = ffma2(p1.x, wa, acc2[1]);
            acc2[1] = ffma2(p1.y, wb, acc2[1]);
            ulonglong2 p2 = h2[32 + q];
            acc2[2] = ffma2(p2.x, wa, acc2[2]);
            acc2[2] = ffma2(p2.y, wb, acc2[2]);
        }
        if (r4) {
#pragma unroll
            for (int q = 0; q < 16; q++) {
                ulonglong2 p3 = h2[48 + q];
                acc2[3] = ffma2(p3.x, w2[2 * q],     acc2[3]);
                acc2[3] = ffma2(p3.y, w2[2 * q + 1], acc2[3]);
            }
        }
        gates_s[0][t] = sum2(acc2[0]);
        gates_s[1][t] = sum2(acc2[1]);
        gates_s[2][t] = sum2(acc2[2]);
        if (r4) gates_s[3][t] = sum2(acc2[3]);
        __syncthreads();

        // elementwise LSTM cell: one cell per thread
        if (cell) {
            float iv = sigf(gates_s[re][je]);
            float fv = sigf(gates_s[re][64 + je]);
            float gv = tanh_fast(gates_s[re][128 + je]);
            float ov = sigf(gates_s[re][192 + je]);
            c = fmaf(fv, c, iv * gv);
            float hv = ov * tanh_fast(c);
            h_s[re][je] = hv;
            h_last = hv;
            if (mode != 2)
                g_h[((size_t)(b0 + re) * T_SZ + step) * H_SZ + je] = hv;
        }
        __syncthreads();
    }

    // mode 2: fused FC — out[b0+re] = sum_je h_last*wfc[je] + bfc[0]
    if (mode == 2) {
        float p = cell ? h_last * wfc[je] : 0.0f;
#pragma unroll
        for (int off = 16; off; off >>= 1)
            p += __shfl_down_sync(0xFFFFFFFFu, p, off);
        if ((t & 31) == 0) gates_s[0][t >> 5] = p;   // one value per warp
        __syncthreads();
        if (t < rows)
            out[b0 + t] = gates_s[0][2 * t] + gates_s[0][2 * t + 1] + bfc[0];
    }
}

// ---------------------------------------------------------------------------
extern "C" void kernel_launch(void* const* d_in, const int* in_sizes, int n_in,
                              void* d_out, int out_size)
{
    (void)in_sizes; (void)n_in; (void)out_size;
    const float* x     = (const float*)d_in[0];
    const float* w_ih0 = (const float*)d_in[1];
    const float* w_hh0 = (const float*)d_in[2];
    const float* b_ih0 = (const float*)d_in[3];
    const float* b_hh0 = (const float*)d_in[4];
    const float* w_ih1 = (const float*)d_in[5];
    const float* w_hh1 = (const float*)d_in[6];
    const float* b_ih1 = (const float*)d_in[7];
    const float* b_hh1 = (const float*)d_in[8];
    const float* w_ih2 = (const float*)d_in[9];
    const float* w_hh2 = (const float*)d_in[10];
    const float* b_ih2 = (const float*)d_in[11];
    const float* b_hh2 = (const float*)d_in[12];
    const float* w_fc  = (const float*)d_in[13];
    const float* b_fc  = (const float*)d_in[14];
    float* out = (float*)d_out;

    const int NROWS = B_SZ * T_SZ;  // 262144

    cudaFuncSetAttribute(xg_gemm64, cudaFuncAttributeMaxDynamicSharedMemorySize,
                         XG_SMEM_BYTES);

    // both weight transposes upfront (independent of everything else)
    transpose_w2<<<128, 256>>>(w_ih1, w_ih2);

    // layer 0 (xg fused into rec)
    lstm_rec<<<GRID_REC, 256>>>(w_hh0, x, w_ih0, b_ih0, b_hh0,
                                nullptr, nullptr, nullptr, 0);

    // layer 1
    xg_gemm64<<<NROWS / 64, 256, XG_SMEM_BYTES>>>(b_ih1, b_hh1, 0);
    lstm_rec<<<GRID_REC, 256>>>(w_hh1, nullptr, nullptr, nullptr, nullptr,
                                nullptr, nullptr, nullptr, 1);

    // layer 2 (+ fused FC)
    xg_gemm64<<<NROWS / 64, 256, XG_SMEM_BYTES>>>(b_ih2, b_hh2, 1);
    lstm_rec<<<GRID_REC, 256>>>(w_hh2, nullptr, nullptr, nullptr, nullptr,
                                w_fc, b_fc, out, 2);
}

// round 10
// speedup vs baseline: 1.2358x; 1.0511x over previous
#include <cuda_runtime.h>

// LSTMModel: B=1024, T=256, I=5, H=64, L=3, O=1, fp32.
// R9: R8 baseline (R4 rec + fused FC + merged transpose, stagger removed)
// + xg_gemm64 bank-conflict fix: thread owns gates {4*tcol..+3} and
// {128+4*tcol..+3} so b-reads are warp-dense conflict-free LDS.128
// (previously 8*tcol ownership -> 32B lane stride -> ~8-way conflicts,
// L1 at 90%). Bitwise-identical math.

#define B_SZ 1024
#define T_SZ 256
#define I_SZ 5
#define H_SZ 64
#define G_SZ 256   // 4*H
#define N4   112           // CTAs carrying 4 rows; rest carry 3
#define GRID_REC 304       // 112*4 + 192*3 = 1024

typedef unsigned long long u64;

__device__ float g_xg[(size_t)B_SZ * T_SZ * G_SZ];  // gate preactivations (layers 1,2)
__device__ float g_h [(size_t)B_SZ * T_SZ * H_SZ];  // layer outputs
__device__ float g_wT1[H_SZ * G_SZ];                // transposed w_ih1
__device__ float g_wT2[H_SZ * G_SZ];                // transposed w_ih2

__device__ __forceinline__ u64 ffma2(u64 a, u64 b, u64 c) {
    u64 d;
    asm("fma.rn.f32x2 %0, %1, %2, %3;" : "=l"(d) : "l"(a), "l"(b), "l"(c));
    return d;
}
__device__ __forceinline__ u64 pack2(float lo, float hi) {
    u64 d;
    asm("mov.b64 %0, {%1, %2};" : "=l"(d) : "f"(lo), "f"(hi));
    return d;
}
__device__ __forceinline__ float sum2(u64 v) {
    float lo, hi;
    asm("mov.b64 {%0, %1}, %2;" : "=f"(lo), "=f"(hi) : "l"(v));
    return lo + hi;
}

__device__ __forceinline__ float sigf(float x) {
    return __fdividef(1.0f, 1.0f + __expf(-x));
}
__device__ __forceinline__ float tanh_fast(float x) {
    float ax = fabsf(x);
    float e  = __expf(-2.0f * ax);
    float r  = __fdividef(1.0f - e, 1.0f + e);
    return copysignf(r, x);
}

// ---------------------------------------------------------------------------
// Transpose w_ih1 AND w_ih2 [256,64] -> g_wT1/g_wT2 [64,256] in one launch.
// ---------------------------------------------------------------------------
__global__ __launch_bounds__(256) void transpose_w2(
    const float* __restrict__ w1, const float* __restrict__ w2)
{
    int idx = blockIdx.x * 256 + threadIdx.x;  // < 32768
    int l = idx >> 14, r = idx & 16383;
    int g = r >> 6, k = r & 63;
    if (l == 0) g_wT1[k * G_SZ + g] = w1[r];
    else        g_wT2[k * G_SZ + g] = w2[r];
}

// ---------------------------------------------------------------------------
// Layers 1/2 input projection: [262144,64] @ [64,256] + bias -> g_xg.
// Dup-pair input tile + conflict-free b-reads: thread (tcol,trow) owns
// gates gA=4*tcol..+3 and gB=128+4*tcol..+3; per k, two warp-dense LDS.128.
// ---------------------------------------------------------------------------
#define XG_W_PITCH 260
#define XG_SMEM_BYTES (64 * 64 * 8 + 64 * XG_W_PITCH * 4)

__global__ __launch_bounds__(256, 2) void xg_gemm64(
    const float* __restrict__ b_ih, const float* __restrict__ b_hh, int which)
{
    extern __shared__ __align__(16) unsigned char smraw[];
    u64   (*a2_s)[64]        = (u64(*)[64])smraw;                      // 32 KB
    float (*w_s)[XG_W_PITCH] = (float(*)[XG_W_PITCH])(smraw + 64 * 64 * 8);
    const float* wT = which ? g_wT2 : g_wT1;

    const int t    = threadIdx.x;
    const int row0 = blockIdx.x * 64;
    const int tcol = t & 31, trow = t >> 5;
    const int gA   = 4 * tcol;          // gates gA..gA+3
    const int gB   = 128 + 4 * tcol;    // gates gB..gB+3

    // input tile [64 rows][64 k] as duplicated pairs
#pragma unroll
    for (int u = 0; u < 4; u++) {
        int v = u * 256 + t;
        int r = v >> 4, kq = v & 15;
        float4 d = *(const float4*)&g_h[(size_t)(row0 + r) * H_SZ + kq * 4];
        ulonglong2 e0, e1;
        e0.x = pack2(d.x, d.x); e0.y = pack2(d.y, d.y);
        e1.x = pack2(d.z, d.z); e1.y = pack2(d.w, d.w);
        *(ulonglong2*)&a2_s[r][kq * 4]     = e0;
        *(ulonglong2*)&a2_s[r][kq * 4 + 2] = e1;
    }
    // weight tile [64][256] from pre-transposed wT
#pragma unroll
    for (int u = 0; u < 16; u++) {
        int v = u * 256 + t;
        int k = v >> 6, gq = v & 63;
        float4 d = *(const float4*)&wT[k * G_SZ + gq * 4];
        *(float4*)&w_s[k][gq * 4] = d;
    }

    // acc2[row][jp]: jp 0,1 = gate pairs (gA,gA+1),(gA+2,gA+3);
    //               jp 2,3 = (gB,gB+1),(gB+2,gB+3)
    u64 acc2[8][4];
    {
        u64 bp[4];
#pragma unroll
        for (int p = 0; p < 2; p++) {
            bp[p]     = pack2(b_ih[gA + 2 * p]     + b_hh[gA + 2 * p],
                              b_ih[gA + 2 * p + 1] + b_hh[gA + 2 * p + 1]);
            bp[2 + p] = pack2(b_ih[gB + 2 * p]     + b_hh[gB + 2 * p],
                              b_ih[gB + 2 * p + 1] + b_hh[gB + 2 * p + 1]);
        }
#pragma unroll
        for (int ii = 0; ii < 8; ii++)
#pragma unroll
            for (int jp = 0; jp < 4; jp++) acc2[ii][jp] = bp[jp];
    }

    __syncthreads();

#pragma unroll 4
    for (int k = 0; k < 64; k++) {
        u64 adup[8];
#pragma unroll
        for (int ii = 0; ii < 8; ii++)
            adup[ii] = a2_s[trow * 8 + ii][k];            // LDS.64 broadcast
        ulonglong2 bvA = *(const ulonglong2*)&w_s[k][gA]; // conflict-free
        ulonglong2 bvB = *(const ulonglong2*)&w_s[k][gB]; // conflict-free
        u64 bp[4] = {bvA.x, bvA.y, bvB.x, bvB.y};
#pragma unroll
        for (int ii = 0; ii < 8; ii++)
#pragma unroll
            for (int jp = 0; jp < 4; jp++)
                acc2[ii][jp] = ffma2(adup[ii], bp[jp], acc2[ii][jp]);
    }

#pragma unroll
    for (int ii = 0; ii < 8; ii++) {
        size_t base = (size_t)(row0 + trow * 8 + ii) * G_SZ;
        ulonglong2 oA, oB;
        oA.x = acc2[ii][0]; oA.y = acc2[ii][1];
        oB.x = acc2[ii][2]; oB.y = acc2[ii][3];
        *(ulonglong2*)&g_xg[base + gA] = oA;   // warp: 512B dense
        *(ulonglong2*)&g_xg[base + gB] = oB;   // warp: 512B dense
    }
}

// ---------------------------------------------------------------------------
// Recurrent scan (R4-exact + fused fc in mode 2).
// Balanced 304-CTA grid (112x4 + 192x3 rows), 256 threads, 2 CTAs/SM.
// ---------------------------------------------------------------------------
__global__ __launch_bounds__(256, 2) void lstm_rec(
    const float* __restrict__ w_hh,
    const float* __restrict__ x,      // mode 0 only
    const float* __restrict__ w_ih,   // mode 0 only [256,5]
    const float* __restrict__ b_ih,   // mode 0 only
    const float* __restrict__ b_hh,   // mode 0 only
    const float* __restrict__ wfc,    // mode 2 only
    const float* __restrict__ bfc,    // mode 2 only
    float* __restrict__ out,          // mode 2 only
    int mode)
{
    __shared__ __align__(16) float h_s[4][H_SZ];     // 1 KB
    __shared__ float gates_s[4][G_SZ];               // 4 KB
    __shared__ float xs[2][4][8];                    // mode-0 x staging
    const int t   = threadIdx.x;                     // gate column
    const int bid = blockIdx.x;
    const bool r4 = (bid < N4);
    const int b0  = r4 ? bid * 4 : N4 * 4 + (bid - N4) * 3;
    const int rows = r4 ? 4 : 3;

    // register-resident recurrent weight pairs (w_hh row t)
    u64 w2[32];
    {
        const ulonglong2* wv = (const ulonglong2*)(w_hh + t * H_SZ);
#pragma unroll
        for (int q = 0; q < 16; q++) {
            ulonglong2 v = wv[q];
            w2[2 * q]     = v.x;
            w2[2 * q + 1] = v.y;
        }
    }

    // mode-0: input weights + bias + step-0 x staging
    float wx[I_SZ];
    float bias = 0.0f;
    if (mode == 0) {
#pragma unroll
        for (int k = 0; k < I_SZ; k++) wx[k] = w_ih[t * I_SZ + k];
        bias = b_ih[t] + b_hh[t];
        if (t < 4 * I_SZ) {
            int r = t / I_SZ, k = t % I_SZ;
            if (r < rows)
                xs[0][r][k] = x[((size_t)(b0 + r) * T_SZ) * I_SZ + k];
        }
    }

    ((float*)h_s)[t] = 0.0f;

    const int re = t >> 6, je = t & 63;
    const bool cell = (t < rows * 64);
    float c = 0.0f;
    float h_last = 0.0f;

    float xn[4];
    if (mode != 0) {
#pragma unroll
        for (int r = 0; r < 3; r++)
            xn[r] = g_xg[((size_t)(b0 + r) * T_SZ) * G_SZ + t];
        xn[3] = r4 ? g_xg[((size_t)(b0 + 3) * T_SZ) * G_SZ + t] : 0.0f;
    }

    __syncthreads();

    for (int step = 0; step < T_SZ; step++) {
        u64 acc2[4];
        if (mode == 0) {
            const int cur = step & 1;
            float a0 = bias, a1 = bias, a2v = bias, a3 = bias;
#pragma unroll
            for (int k = 0; k < I_SZ; k++) {
                a0  = fmaf(xs[cur][0][k], wx[k], a0);
                a1  = fmaf(xs[cur][1][k], wx[k], a1);
                a2v = fmaf(xs[cur][2][k], wx[k], a2v);
                a3  = fmaf(xs[cur][3][k], wx[k], a3);
            }
            acc2[0] = pack2(a0, 0.0f);  acc2[1] = pack2(a1, 0.0f);
            acc2[2] = pack2(a2v, 0.0f); acc2[3] = pack2(a3, 0.0f);
            if (step + 1 < T_SZ && t < 4 * I_SZ) {
                int r = t / I_SZ, k = t % I_SZ;
                if (r < rows)
                    xs[cur ^ 1][r][k] = x[((size_t)(b0 + r) * T_SZ + step + 1) * I_SZ + k];
            }
        } else {
#pragma unroll
            for (int r = 0; r < 4; r++) acc2[r] = pack2(xn[r], 0.0f);
            if (step + 1 < T_SZ) {
#pragma unroll
                for (int r = 0; r < 3; r++)
                    xn[r] = g_xg[((size_t)(b0 + r) * T_SZ + step + 1) * G_SZ + t];
                if (r4)
                    xn[3] = g_xg[((size_t)(b0 + 3) * T_SZ + step + 1) * G_SZ + t];
            }
        }

        // GEMM: gates[r][t] += sum_k h[r][k] * w_hh[t][k]
        const ulonglong2* h2 = (const ulonglong2*)&h_s[0][0];
#pragma unroll
        for (int q = 0; q < 16; q++) {
            const u64 wa = w2[2 * q], wb = w2[2 * q + 1];
            ulonglong2 p0 = h2[q];
            acc2[0] = ffma2(p0.x, wa, acc2[0]);
            acc2[0] = ffma2(p0.y, wb, acc2[0]);
            ulonglong2 p1 = h2[16 + q];
            acc2[1] = ffma2(p1.x, wa, acc2[1]);
            acc2[1] = ffma2(p1.y, wb, acc2[1]);
            ulonglong2 p2 = h2[32 + q];
            acc2[2] = ffma2(p2.x, wa, acc2[2]);
            acc2[2] = ffma2(p2.y, wb, acc2[2]);
        }
        if (r4) {
#pragma unroll
            for (int q = 0; q < 16; q++) {
                ulonglong2 p3 = h2[48 + q];
                acc2[3] = ffma2(p3.x, w2[2 * q],     acc2[3]);
                acc2[3] = ffma2(p3.y, w2[2 * q + 1], acc2[3]);
            }
        }
        gates_s[0][t] = sum2(acc2[0]);
        gates_s[1][t] = sum2(acc2[1]);
        gates_s[2][t] = sum2(acc2[2]);
        if (r4) gates_s[3][t] = sum2(acc2[3]);
        __syncthreads();

        // elementwise LSTM cell: one cell per thread
        if (cell) {
            float iv = sigf(gates_s[re][je]);
            float fv = sigf(gates_s[re][64 + je]);
            float gv = tanh_fast(gates_s[re][128 + je]);
            float ov = sigf(gates_s[re][192 + je]);
            c = fmaf(fv, c, iv * gv);
            float hv = ov * tanh_fast(c);
            h_s[re][je] = hv;
            h_last = hv;
            if (mode != 2)
                g_h[((size_t)(b0 + re) * T_SZ + step) * H_SZ + je] = hv;
        }
        __syncthreads();
    }

    // mode 2: fused FC — out[b0+re] = sum_je h_last*wfc[je] + bfc[0]
    if (mode == 2) {
        float p = cell ? h_last * wfc[je] : 0.0f;
#pragma unroll
        for (int off = 16; off; off >>= 1)
            p += __shfl_down_sync(0xFFFFFFFFu, p, off);
        if ((t & 31) == 0) gates_s[0][t >> 5] = p;   // one value per warp
        __syncthreads();
        if (t < rows)
            out[b0 + t] = gates_s[0][2 * t] + gates_s[0][2 * t + 1] + bfc[0];
    }
}

// ---------------------------------------------------------------------------
extern "C" void kernel_launch(void* const* d_in, const int* in_sizes, int n_in,
                              void* d_out, int out_size)
{
    (void)in_sizes; (void)n_in; (void)out_size;
    const float* x     = (const float*)d_in[0];
    const float* w_ih0 = (const float*)d_in[1];
    const float* w_hh0 = (const float*)d_in[2];
    const float* b_ih0 = (const float*)d_in[3];
    const float* b_hh0 = (const float*)d_in[4];
    const float* w_ih1 = (const float*)d_in[5];
    const float* w_hh1 = (const float*)d_in[6];
    const float* b_ih1 = (const float*)d_in[7];
    const float* b_hh1 = (const float*)d_in[8];
    const float* w_ih2 = (const float*)d_in[9];
    const float* w_hh2 = (const float*)d_in[10];
    const float* b_ih2 = (const float*)d_in[11];
    const float* b_hh2 = (const float*)d_in[12];
    const float* w_fc  = (const float*)d_in[13];
    const float* b_fc  = (const float*)d_in[14];
    float* out = (float*)d_out;

    const int NROWS = B_SZ * T_SZ;  // 262144

    cudaFuncSetAttribute(xg_gemm64, cudaFuncAttributeMaxDynamicSharedMemorySize,
                         XG_SMEM_BYTES);

    // both weight transposes upfront
    transpose_w2<<<128, 256>>>(w_ih1, w_ih2);

    // layer 0 (xg fused into rec)
    lstm_rec<<<GRID_REC, 256>>>(w_hh0, x, w_ih0, b_ih0, b_hh0,
                                nullptr, nullptr, nullptr, 0);

    // layer 1
    xg_gemm64<<<NROWS / 64, 256, XG_SMEM_BYTES>>>(b_ih1, b_hh1, 0);
    lstm_rec<<<GRID_REC, 256>>>(w_hh1, nullptr, nullptr, nullptr, nullptr,
                                nullptr, nullptr, nullptr, 1);

    // layer 2 (+ fused FC)
    xg_gemm64<<<NROWS / 64, 256, XG_SMEM_BYTES>>>(b_ih2, b_hh2, 1);
    lstm_rec<<<GRID_REC, 256>>>(w_hh2, nullptr, nullptr, nullptr, nullptr,
                                w_fc, b_fc, out, 2);
}